// round 1
// baseline (speedup 1.0000x reference)
#include <cuda_runtime.h>
#include <cstdint>

// Problem constants
namespace {
constexpr int B_ = 4, K_ = 4, G_ = 8, C_ = 64, W_ = 64, H_ = 64;
constexpr int FG_ = 32;                          // output features per group
constexpr int WELEM_PER_G = C_ * FG_ * 16;       // 32768 floats = 128 KB per group
constexpr int STAGE_STRIDE = 516;                // 512 + 4 pad: bank-conflict-free transpose
constexpr int THREADS = 512;                     // 16 warps = 16 positions per iteration
constexpr int CTAS_PER_G = 128;
constexpr int HBLK_PER_G = B_ * W_ * (H_ / 8);   // 2048 blocks of 8 h-positions
constexpr int HBLK_PER_CTA = HBLK_PER_G / CTAS_PER_G;  // 16
constexpr int ITERS = HBLK_PER_CTA / 2;          // 8 (two h-blocks per iteration)
constexpr size_t SMEM_BYTES = (size_t)(WELEM_PER_G + 16 * STAGE_STRIDE) * sizeof(float); // 164096 B

__device__ __forceinline__ void fma4(float4& a, float v, float4 w) {
    a.x = fmaf(v, w.x, a.x);
    a.y = fmaf(v, w.y, a.y);
    a.z = fmaf(v, w.z, a.z);
    a.w = fmaf(v, w.w, a.w);
}

__global__ void __launch_bounds__(THREADS, 1)
deconv_deindex_kernel(const int* __restrict__ indp, const int* __restrict__ indn,
                      const float* __restrict__ valp, const float* __restrict__ valn,
                      const float* __restrict__ wgt, float* __restrict__ out)
{
    extern __shared__ float sm[];
    float* Wsm   = sm;                  // [64 channels][512 floats] for this group
    float* stage = sm + WELEM_PER_G;    // [16 positions][516 floats]

    const int tid  = threadIdx.x;
    const int lane = tid & 31;
    const int wp   = tid >> 5;

    const int g  = blockIdx.x / CTAS_PER_G;
    const int cg = blockIdx.x - g * CTAS_PER_G;

    // Load this group's 128 KB weight slice into shared memory (coalesced float4).
    {
        const float4* src = reinterpret_cast<const float4*>(wgt) + (size_t)g * (WELEM_PER_G / 4);
        float4* dst = reinterpret_cast<float4*>(Wsm);
        #pragma unroll
        for (int i = 0; i < WELEM_PER_G / 4 / THREADS; i++)
            dst[i * THREADS + tid] = src[i * THREADS + tid];
    }
    __syncthreads();

    const int KS = G_ * W_ * H_;  // k-stride in index/value tensors (32768)

    for (int it = 0; it < ITERS; it++) {
        // This iteration covers two adjacent 8-position h-blocks (shared b, w).
        const int hpb  = cg * HBLK_PER_CTA + it * 2;  // even h-block index
        const int hblk = hpb + (wp >> 3);
        const int hb = hblk & 7;
        const int w  = (hblk >> 3) & 63;
        const int b  = hblk >> 9;
        const int h  = hb * 8 + (wp & 7);

        const int base = (((b * K_) * G_ + g) * W_ + w) * H_ + h;

        // Load this position's 8 scatter entries (warp-uniform broadcast loads).
        int   ind[8];
        float val[8];
        #pragma unroll
        for (int k = 0; k < 4; k++) {
            ind[k]     = __ldg(indp + base + k * KS);
            val[k]     = __ldg(valp + base + k * KS);
            ind[4 + k] = __ldg(indn + base + k * KS);
            val[4 + k] = __ldg(valn + base + k * KS);
        }

        // Scatter "last write wins" (k ascending within pos-scatter, then neg-scatter
        // overwrites): entry t survives iff no later entry targets the same channel.
        unsigned keep = 0;
        #pragma unroll
        for (int t = 0; t < 8; t++) {
            bool kp = true;
            #pragma unroll
            for (int u = t + 1; u < 8; u++) kp = kp && (ind[u] != ind[t]);
            keep |= (unsigned)kp << t;
        }

        // Accumulate 16 outputs per lane: lane l owns weight-row quarters
        // q*128 + 4l .. +3  (q = 0..3)  => (f = 8q + l/4, taps (l%4)*4 .. +3).
        float4 a0 = {0.f, 0.f, 0.f, 0.f}, a1 = a0, a2 = a0, a3 = a0;
        #pragma unroll
        for (int t = 0; t < 8; t++) {
            if (!((keep >> t) & 1)) continue;
            const float* wrow = Wsm + ind[t] * 512 + lane * 4;
            const float v = val[t];
            float4 w0 = *reinterpret_cast<const float4*>(wrow);
            float4 w1 = *reinterpret_cast<const float4*>(wrow + 128);
            float4 w2 = *reinterpret_cast<const float4*>(wrow + 256);
            float4 w3 = *reinterpret_cast<const float4*>(wrow + 384);
            fma4(a0, v, w0);
            fma4(a1, v, w1);
            fma4(a2, v, w2);
            fma4(a3, v, w3);
        }

        // Stage: stage[wp][0..511] holds this position's 512 outputs in
        // weight-row order (f*16 + i*4 + j). Conflict-free (consecutive lanes).
        {
            float* srow = stage + wp * STAGE_STRIDE + lane * 4;
            *reinterpret_cast<float4*>(srow)       = a0;
            *reinterpret_cast<float4*>(srow + 128) = a1;
            *reinterpret_cast<float4*>(srow + 256) = a2;
            *reinterpret_cast<float4*>(srow + 384) = a3;
        }
        __syncthreads();

        // Cooperative coalesced store: 2048 float4s. Output row (f,i) spans
        // oh = 32*hb0 + 4*e + j for e = 0..15 -> 256 B contiguous runs,
        // full 128 B lines (no L2 read-for-ownership).
        {
            const int b2  = hpb >> 9;
            const int w2  = (hpb >> 3) & 63;
            const int hb0 = hpb & 7;  // even
            float* obase = out + (((size_t)b2 * 256 + g * 32) * 256 + 4 * w2) * 256 + hb0 * 32;
            #pragma unroll
            for (int rr = 0; rr < 4; rr++) {
                const int idx = rr * THREADS + tid;   // 0..2047
                const int row = idx >> 4;             // f*4 + i  (0..127)
                const int e   = idx & 15;             // position within the block pair
                float4 vv = *reinterpret_cast<const float4*>(stage + e * STAGE_STRIDE + row * 4);
                const int f = row >> 2;
                const int i = row & 3;
                *reinterpret_cast<float4*>(obase + ((size_t)f * 256 + i) * 256 + e * 4) = vv;
            }
        }
        __syncthreads();  // protect stage before next iteration overwrites it
    }
}
}  // namespace

extern "C" void kernel_launch(void* const* d_in, const int* in_sizes, int n_in,
                              void* d_out, int out_size) {
    const int*   indp = (const int*)d_in[0];
    const int*   indn = (const int*)d_in[1];
    const float* valp = (const float*)d_in[2];
    const float* valn = (const float*)d_in[3];
    const float* wgt  = (const float*)d_in[4];
    float* out = (float*)d_out;

    cudaFuncSetAttribute(deconv_deindex_kernel,
                         cudaFuncAttributeMaxDynamicSharedMemorySize, (int)SMEM_BYTES);
    deconv_deindex_kernel<<<G_ * CTAS_PER_G, THREADS, SMEM_BYTES>>>(
        indp, indn, valp, valn, wgt, out);
}

// round 2
// speedup vs baseline: 1.1453x; 1.1453x over previous
#include <cuda_runtime.h>
#include <cstdint>

// Problem constants
namespace {
constexpr int B_ = 4, K_ = 4, G_ = 8, W_ = 64, H_ = 64;
constexpr int THREADS = 512;                       // 16 warps = 16 positions per iteration
constexpr int NQ = 4;                              // feature-quarter split (8 of 32 features)
constexpr int WROW = 128;                          // floats per channel row in the quarter slice
constexpr int WELEM_Q = 64 * WROW;                 // 8192 floats = 32 KB per (g, fq)
constexpr int STAGE_STRIDE = WROW + 4;             // 132: conflict-free transpose
constexpr int CTAS_PER_GQ = 128;
constexpr int HBLK_PER_CTA = 16;                   // 2048 h-blocks per g / 128 CTAs
constexpr int ITERS = HBLK_PER_CTA / 2;            // 8 (two h-blocks = 16 positions per iter)
constexpr size_t SMEM_BYTES = (size_t)(WELEM_Q + 16 * STAGE_STRIDE) * sizeof(float); // 41216 B

__device__ __forceinline__ void fma4(float4& a, float v, float4 w) {
    a.x = fmaf(v, w.x, a.x);
    a.y = fmaf(v, w.y, a.y);
    a.z = fmaf(v, w.z, a.z);
    a.w = fmaf(v, w.w, a.w);
}

__global__ void __launch_bounds__(THREADS, 3)
deconv_deindex_kernel(const int* __restrict__ indp, const int* __restrict__ indn,
                      const float* __restrict__ valp, const float* __restrict__ valn,
                      const float* __restrict__ wgt, float* __restrict__ out)
{
    extern __shared__ float sm[];
    float* Wsm   = sm;                 // [64 c][128 floats] : this (g, fq) weight slice
    float* stage = sm + WELEM_Q;       // [16 positions][132 floats]

    const int tid  = threadIdx.x;
    const int lane = tid & 31;
    const int wp   = tid >> 5;

    const int bx  = blockIdx.x;
    const int g   = bx >> 9;                       // 512 CTAs per group
    const int rem = bx & 511;
    const int fq  = rem >> 7;                      // feature quarter 0..3
    const int cg  = rem & 127;

    // Load weight slice: Wsm[c*128 + x] = wgt[g*32768 + c*512 + fq*128 + x]
    {
        const float4* wsrc = reinterpret_cast<const float4*>(wgt)
                           + (size_t)g * 8192 + (size_t)fq * 32;
        float4* dst = reinterpret_cast<float4*>(Wsm);
        #pragma unroll
        for (int i = 0; i < WELEM_Q / 4 / THREADS; i++) {
            const int idx = i * THREADS + tid;     // 0..2047
            const int c   = idx >> 5;
            const int x4  = idx & 31;
            dst[idx] = wsrc[(size_t)c * 128 + x4];
        }
    }
    __syncthreads();

    const int KS = G_ * W_ * H_;                   // k-stride (32768)

    for (int it = 0; it < ITERS; it++) {
        const int hpb  = cg * HBLK_PER_CTA + it * 2;   // even h-block index within group
        const int hblk = hpb + (wp >> 3);
        const int hb = hblk & 7;
        const int w  = (hblk >> 3) & 63;
        const int b  = hblk >> 9;
        const int h  = hb * 8 + (wp & 7);

        const int base = (((b * K_) * G_ + g) * W_ + w) * H_ + h;

        // 8 scatter entries for this position (warp-uniform broadcast loads).
        int   ind[8];
        float val[8];
        #pragma unroll
        for (int k = 0; k < 4; k++) {
            ind[k]     = __ldg(indp + base + k * KS);
            val[k]     = __ldg(valp + base + k * KS);
            ind[4 + k] = __ldg(indn + base + k * KS);
            val[4 + k] = __ldg(valn + base + k * KS);
        }

        // Last-write-wins dedup: entry t survives iff no later entry hits same channel.
        // Zero dead values -> branch-free inner loop.
        #pragma unroll
        for (int t = 0; t < 7; t++) {
            bool kp = true;
            #pragma unroll
            for (int u = t + 1; u < 8; u++) kp = kp && (ind[u] != ind[t]);
            val[t] = kp ? val[t] : 0.0f;
        }

        // Accumulate 4 outputs per lane: lane l owns (f_local = l/4, i = l%4, j = 0..3).
        float4 acc = {0.f, 0.f, 0.f, 0.f};
        #pragma unroll
        for (int t = 0; t < 8; t++) {
            const float4 ww = *reinterpret_cast<const float4*>(
                Wsm + ind[t] * WROW + lane * 4);
            fma4(acc, val[t], ww);
        }

        // Stage this position's 128 outputs in weight-row order (f_local*16 + i*4 + j).
        *reinterpret_cast<float4*>(stage + wp * STAGE_STRIDE + lane * 4) = acc;
        __syncthreads();

        // Cooperative coalesced store: 512 float4s, one per thread.
        // Warp = two 256B contiguous runs along oh. Full 128B lines.
        {
            const int b2  = hpb >> 9;
            const int w2  = (hpb >> 3) & 63;
            const int hb0 = hpb & 7;               // even
            float* obase = out + (((size_t)b2 * 256 + g * 32 + fq * 8) * 256
                                  + 4 * w2) * 256 + hb0 * 32;
            const int row = tid >> 4;              // f_local*4 + i  (0..31)
            const int e   = tid & 15;              // position within the 2-block pair
            const float4 vv = *reinterpret_cast<const float4*>(
                stage + e * STAGE_STRIDE + row * 4);
            const int fl = row >> 2;
            const int i  = row & 3;
            *reinterpret_cast<float4*>(obase + ((size_t)fl * 256 + i) * 256 + e * 4) = vv;
        }
        __syncthreads();                           // protect stage for next iteration
    }
}
}  // namespace

extern "C" void kernel_launch(void* const* d_in, const int* in_sizes, int n_in,
                              void* d_out, int out_size) {
    const int*   indp = (const int*)d_in[0];
    const int*   indn = (const int*)d_in[1];
    const float* valp = (const float*)d_in[2];
    const float* valn = (const float*)d_in[3];
    const float* wgt  = (const float*)d_in[4];
    float* out = (float*)d_out;

    cudaFuncSetAttribute(deconv_deindex_kernel,
                         cudaFuncAttributeMaxDynamicSharedMemorySize, (int)SMEM_BYTES);
    cudaFuncSetAttribute(deconv_deindex_kernel,
                         cudaFuncAttributePreferredSharedMemoryCarveout, 100);
    deconv_deindex_kernel<<<G_ * NQ * CTAS_PER_GQ, THREADS, SMEM_BYTES>>>(
        indp, indn, valp, valn, wgt, out);
}

// round 5
// speedup vs baseline: 1.4269x; 1.2459x over previous
#include <cuda_runtime.h>
#include <cuda_fp16.h>
#include <cstdint>

namespace {
constexpr int B_ = 4, K_ = 4, G_ = 8, W_ = 64, H_ = 64;
constexpr int THREADS = 512;                    // 16 warps = 16 positions per iteration
constexpr int WROW_H = 256;                     // halfs per channel row (16 feat x 16 taps)
constexpr int WFLOATS = 64 * WROW_H / 2;        // smem words for weights (8192 = 32 KB)
constexpr int STAGE_STRIDE = 260;               // floats; 65 = 1 mod 8 -> conflict-free reads
constexpr int CTAS_PER_GF = 128;
constexpr int HBLK_PER_CTA = 16;
constexpr int ITERS = 8;                        // two h-blocks (16 positions) per iter
constexpr size_t SMEM_BYTES =
    (size_t)(WFLOATS + 16 * STAGE_STRIDE) * sizeof(float);  // 49408 B -> 3 CTAs/SM

__device__ __forceinline__ unsigned pack_half2(float a, float b) {
    __half2 h = __floats2half2_rn(a, b);
    return *reinterpret_cast<unsigned*>(&h);
}

__global__ void __launch_bounds__(THREADS, 3)
deconv_deindex_kernel(const int* __restrict__ indp, const int* __restrict__ indn,
                      const float* __restrict__ valp, const float* __restrict__ valn,
                      const float* __restrict__ wgt, float* __restrict__ out)
{
    extern __shared__ float sm[];
    __half* Wh   = reinterpret_cast<__half*>(sm);   // [64 ch][256 halfs] this (g, fh) slice
    float*  stage = sm + WFLOATS;                   // [16 positions][260 floats]

    const int tid  = threadIdx.x;
    const int lane = tid & 31;
    const int wp   = tid >> 5;

    const int bx  = blockIdx.x;
    const int g   = bx >> 8;                        // 256 CTAs per group
    const int rem = bx & 255;
    const int fh  = rem >> 7;                       // feature half 0..1 (16 features each)
    const int cg  = rem & 127;

    // Load + convert weight slice: Wh[c*256 + t] = (half)wgt[g*32768 + c*512 + fh*256 + t]
    {
        const float4* wsrc = reinterpret_cast<const float4*>(wgt);
        uint2* wdst = reinterpret_cast<uint2*>(Wh);
        #pragma unroll
        for (int i = 0; i < 8; i++) {
            const int idx = i * THREADS + tid;      // 0..4095 float4 chunks
            const int c   = idx >> 6;
            const int q   = idx & 63;               // float4 within 256-tap row
            float4 v = wsrc[(size_t)g * 8192 + (size_t)c * 128 + fh * 64 + q];
            wdst[c * 64 + q] = make_uint2(pack_half2(v.x, v.y), pack_half2(v.z, v.w));
        }
    }
    __syncthreads();

    const int KS = G_ * W_ * H_;                    // k-stride (32768)
    const int swz = ((lane >> 2) & 1) << 2;         // stage STS bank swizzle (word units)

    for (int it = 0; it < ITERS; it++) {
        const int hpb  = cg * HBLK_PER_CTA + it * 2;    // even h-block index within group
        const int hblk = hpb + (wp >> 3);
        const int hb = hblk & 7;
        const int w  = (hblk >> 3) & 63;
        const int b  = hblk >> 9;
        const int h  = hb * 8 + (wp & 7);

        const int base = (((b * K_) * G_ + g) * W_ + w) * H_ + h;

        // 8 scatter entries (warp-uniform broadcast loads).
        int ind[8];
        #pragma unroll
        for (int k = 0; k < 4; k++) {
            ind[k]     = __ldg(indp + base + k * KS);
            ind[4 + k] = __ldg(indn + base + k * KS);
        }

        // Last-write-wins dedup mask: entry t survives iff no later entry hits channel.
        unsigned km = 0xFFu;
        #pragma unroll
        for (int t = 0; t < 7; t++) {
            bool dup = false;
            #pragma unroll
            for (int u = t + 1; u < 8; u++) dup = dup || (ind[u] == ind[t]);
            if (dup) km &= ~(1u << t);
        }

        // Lane owns 8 outputs: taps [8*lane, 8*lane+8) of the 256-tap row.
        float a0 = 0.f, a1 = 0.f, a2 = 0.f, a3 = 0.f;
        float a4 = 0.f, a5 = 0.f, a6 = 0.f, a7 = 0.f;
        #pragma unroll
        for (int t = 0; t < 8; t++) {
            const float* vp = (t < 4) ? (valp + base + t * KS)
                                      : (valn + base + (t - 4) * KS);
            float v = __ldg(vp);
            v = ((km >> t) & 1) ? v : 0.0f;
            uint4 u = *reinterpret_cast<const uint4*>(
                Wh + ind[t] * WROW_H + lane * 8);
            float2 f0 = __half22float2(*reinterpret_cast<const __half2*>(&u.x));
            float2 f1 = __half22float2(*reinterpret_cast<const __half2*>(&u.y));
            float2 f2 = __half22float2(*reinterpret_cast<const __half2*>(&u.z));
            float2 f3 = __half22float2(*reinterpret_cast<const __half2*>(&u.w));
            a0 = fmaf(v, f0.x, a0); a1 = fmaf(v, f0.y, a1);
            a2 = fmaf(v, f1.x, a2); a3 = fmaf(v, f1.y, a3);
            a4 = fmaf(v, f2.x, a4); a5 = fmaf(v, f2.y, a5);
            a6 = fmaf(v, f3.x, a6); a7 = fmaf(v, f3.y, a7);
        }

        // Stage (swizzled): lane owns words [8l, 8l+8); the XOR swaps its two
        // float4 halves for lanes with swz=4 (stays inside the lane's region).
        {
            float* srow = stage + wp * STAGE_STRIDE;
            *reinterpret_cast<float4*>(srow + ((lane * 8) ^ swz))
                = make_float4(a0, a1, a2, a3);
            *reinterpret_cast<float4*>(srow + ((lane * 8 + 4) ^ swz))
                = make_float4(a4, a5, a6, a7);
        }
        __syncthreads();

        // Cooperative coalesced store: 1024 float4s, 2 per thread.
        {
            const int b2  = hpb >> 9;
            const int w2  = (hpb >> 3) & 63;
            const int hb0 = hpb & 7;                 // even
            float* obase = out + (((size_t)b2 * 256 + g * 32 + fh * 16) * 256
                                  + 4 * w2) * 256 + hb0 * 32;
            #pragma unroll
            for (int r = 0; r < 2; r++) {
                const int idx = r * THREADS + tid;   // 0..1023
                const int row = idx >> 4;            // f_local*4 + i  (0..63)
                const int e   = idx & 15;            // position 0..15 (= oh block)
                const int sw  = (row * 4) ^ ((((unsigned)row >> 3) & 1) << 2);
                const float4 vv = *reinterpret_cast<const float4*>(
                    stage + e * STAGE_STRIDE + sw);
                const int f = row >> 2;
                const int i = row & 3;
                *reinterpret_cast<float4*>(
                    obase + ((size_t)f * 256 + i) * 256 + e * 4) = vv;
            }
        }
        __syncthreads();                             // protect stage for next iteration
    }
}
}  // namespace

extern "C" void kernel_launch(void* const* d_in, const int* in_sizes, int n_in,
                              void* d_out, int out_size) {
    const int*   indp = (const int*)d_in[0];
    const int*   indn = (const int*)d_in[1];
    const float* valp = (const float*)d_in[2];
    const float* valn = (const float*)d_in[3];
    const float* wgt  = (const float*)d_in[4];
    float* out = (float*)d_out;

    cudaFuncSetAttribute(deconv_deindex_kernel,
                         cudaFuncAttributeMaxDynamicSharedMemorySize, (int)SMEM_BYTES);
    cudaFuncSetAttribute(deconv_deindex_kernel,
                         cudaFuncAttributePreferredSharedMemoryCarveout, 100);
    deconv_deindex_kernel<<<G_ * 2 * CTAS_PER_GF, THREADS, SMEM_BYTES>>>(
        indp, indn, valp, valn, wgt, out);
}

// round 6
// speedup vs baseline: 1.7190x; 1.2047x over previous
#include <cuda_runtime.h>
#include <cuda_fp16.h>
#include <cstdint>

namespace {
constexpr int B_ = 4, K_ = 4, G_ = 8, W_ = 64, H_ = 64;
constexpr int THREADS = 512;                    // 16 warps = 16 positions per iteration
constexpr int WROW_H = 256;                     // halfs per channel row (16 feat x 16 taps)
constexpr int WFLOATS = 64 * WROW_H / 2;        // smem floats for weights (8192 = 32 KB)
constexpr int SH = 264;                         // stage stride in halfs (132 words = 4 mod 32)
constexpr int CTAS_PER_GF = 128;
constexpr int HBLK_PER_CTA = 16;
constexpr int ITERS = 8;                        // two h-blocks (16 positions) per iter
constexpr size_t SMEM_BYTES =
    (size_t)WFLOATS * 4 + (size_t)16 * SH * 2;  // 32768 + 8448 = 41216 B -> 3 CTAs/SM

__device__ __forceinline__ unsigned pack_half2(float a, float b) {
    __half2 h = __floats2half2_rn(a, b);
    return *reinterpret_cast<unsigned*>(&h);
}

__global__ void __launch_bounds__(THREADS, 3)
deconv_deindex_kernel(const int* __restrict__ indp, const int* __restrict__ indn,
                      const float* __restrict__ valp, const float* __restrict__ valn,
                      const float* __restrict__ wgt, float* __restrict__ out)
{
    extern __shared__ float sm[];
    __half* Wh     = reinterpret_cast<__half*>(sm);          // [64 ch][256 halfs]
    __half* stageH = reinterpret_cast<__half*>(sm + WFLOATS); // [16 pos][264 halfs]

    const int tid  = threadIdx.x;
    const int lane = tid & 31;
    const int wp   = tid >> 5;

    const int bx  = blockIdx.x;
    const int g   = bx >> 8;                        // 256 CTAs per group
    const int rem = bx & 255;
    const int fh  = rem >> 7;                       // feature half 0..1 (16 features each)
    const int cg  = rem & 127;

    // Load + convert weight slice: Wh[c*256 + t] = (half)wgt[g*32768 + c*512 + fh*256 + t]
    {
        const float4* wsrc = reinterpret_cast<const float4*>(wgt);
        uint2* wdst = reinterpret_cast<uint2*>(Wh);
        #pragma unroll
        for (int i = 0; i < 8; i++) {
            const int idx = i * THREADS + tid;      // 0..4095 float4 chunks
            const int c   = idx >> 6;
            const int q   = idx & 63;               // float4 within 256-tap row
            float4 v = wsrc[(size_t)g * 8192 + (size_t)c * 128 + fh * 64 + q];
            wdst[c * 64 + q] = make_uint2(pack_half2(v.x, v.y), pack_half2(v.z, v.w));
        }
    }
    __syncthreads();

    const int KS = G_ * W_ * H_;                    // k-stride (32768)

    for (int it = 0; it < ITERS; it++) {
        const int hpb  = cg * HBLK_PER_CTA + it * 2;    // even h-block index within group
        const int hblk = hpb + (wp >> 3);
        const int hb = hblk & 7;
        const int w  = (hblk >> 3) & 63;
        const int b  = hblk >> 9;
        const int h  = hb * 8 + (wp & 7);

        const int base = (((b * K_) * G_ + g) * W_ + w) * H_ + h;

        // 8 scatter entries (warp-uniform broadcast loads).
        int ind[8];
        #pragma unroll
        for (int k = 0; k < 4; k++) {
            ind[k]     = __ldg(indp + base + k * KS);
            ind[4 + k] = __ldg(indn + base + k * KS);
        }

        // Last-write-wins dedup: entry t survives iff no later entry hits its channel.
        unsigned km = 0xFFu;
        #pragma unroll
        for (int t = 0; t < 7; t++) {
            bool dup = false;
            #pragma unroll
            for (int u = t + 1; u < 8; u++) dup = dup || (ind[u] == ind[t]);
            if (dup) km &= ~(1u << t);
        }

        // Lane owns taps [8*lane, 8*lane+8); accumulate in fp16 pairs (HFMA2).
        __half2 a0 = __float2half2_rn(0.f), a1 = a0, a2 = a0, a3 = a0;
        #pragma unroll
        for (int t = 0; t < 8; t++) {
            const float* vp = (t < 4) ? (valp + base + t * KS)
                                      : (valn + base + (t - 4) * KS);
            float v = __ldg(vp);
            v = ((km >> t) & 1) ? v : 0.0f;
            const __half2 vv = __float2half2_rn(v);
            uint4 u = *reinterpret_cast<const uint4*>(Wh + ind[t] * WROW_H + lane * 8);
            a0 = __hfma2(vv, *reinterpret_cast<const __half2*>(&u.x), a0);
            a1 = __hfma2(vv, *reinterpret_cast<const __half2*>(&u.y), a1);
            a2 = __hfma2(vv, *reinterpret_cast<const __half2*>(&u.z), a2);
            a3 = __hfma2(vv, *reinterpret_cast<const __half2*>(&u.w), a3);
        }

        // Stage in fp16: lane writes its 8 taps contiguously (conflict-free STS.128).
        {
            uint4 pk;
            pk.x = *reinterpret_cast<unsigned*>(&a0);
            pk.y = *reinterpret_cast<unsigned*>(&a1);
            pk.z = *reinterpret_cast<unsigned*>(&a2);
            pk.w = *reinterpret_cast<unsigned*>(&a3);
            *reinterpret_cast<uint4*>(stageH + wp * SH + lane * 8) = pk;
        }
        __syncthreads();

        // Store phase: 512 items, one per thread. Item = (position e, tap-chunk c of 8).
        // Read LDS.128 (conflict-free: 132-word stride), convert 8 halfs, 2x STG.128.
        {
            const int b2  = hpb >> 9;
            const int w2  = (hpb >> 3) & 63;
            const int hb0 = hpb & 7;                 // even
            float* obase = out + (((size_t)b2 * 256 + g * 32 + fh * 16) * 256
                                  + 4 * w2) * 256 + hb0 * 32;
            const int e = tid & 15;                  // position 0..15 (oh block)
            const int c = tid >> 4;                  // tap chunk 0..31 (taps 8c..8c+7)
            uint4 u = *reinterpret_cast<const uint4*>(stageH + e * SH + c * 8);
            float2 f0 = __half22float2(*reinterpret_cast<const __half2*>(&u.x));
            float2 f1 = __half22float2(*reinterpret_cast<const __half2*>(&u.y));
            float2 f2 = __half22float2(*reinterpret_cast<const __half2*>(&u.z));
            float2 f3 = __half22float2(*reinterpret_cast<const __half2*>(&u.w));
            const int f  = c >> 1;                   // feature 0..15
            const int i0 = (c & 1) * 2;              // kernel-row pair base
            float* p0 = obase + ((size_t)f * 256 + i0) * 256 + e * 4;
            *reinterpret_cast<float4*>(p0)       = make_float4(f0.x, f0.y, f1.x, f1.y);
            *reinterpret_cast<float4*>(p0 + 256) = make_float4(f2.x, f2.y, f3.x, f3.y);
        }
        __syncthreads();                             // protect stage for next iteration
    }
}
}  // namespace

extern "C" void kernel_launch(void* const* d_in, const int* in_sizes, int n_in,
                              void* d_out, int out_size) {
    const int*   indp = (const int*)d_in[0];
    const int*   indn = (const int*)d_in[1];
    const float* valp = (const float*)d_in[2];
    const float* valn = (const float*)d_in[3];
    const float* wgt  = (const float*)d_in[4];
    float* out = (float*)d_out;

    cudaFuncSetAttribute(deconv_deindex_kernel,
                         cudaFuncAttributeMaxDynamicSharedMemorySize, (int)SMEM_BYTES);
    cudaFuncSetAttribute(deconv_deindex_kernel,
                         cudaFuncAttributePreferredSharedMemoryCarveout, 100);
    deconv_deindex_kernel<<<G_ * 2 * CTAS_PER_GF, THREADS, SMEM_BYTES>>>(
        indp, indn, valp, valn, wgt, out);
}